// round 4
// baseline (speedup 1.0000x reference)
#include <cuda_runtime.h>
#include <cuda_bf16.h>
#include <cstdint>

// Problem constants (fixed shapes per reference)
#define Bn   8
#define Nn   1024
#define Fin  128
#define Cc   128
#define Ef   64
#define Hh   4
#define NEG  0.2f
#define ROWS (Bn * Nn)          // 8192

// Scratch (device globals — no allocation allowed)
__device__ float  g_M[Fin * 12];            // cols 0-3: As, 4-7: Ad, 8-11: Ae
__device__ float4 g_S [ROWS];               // s  = src @ As   (linear)
__device__ float4 g_D [ROWS];               // d  = src @ Ad   (linear)
__device__ float4 g_P [ROWS];               // p  = src @ Ae   (linear)
__device__ float4 g_ES [ROWS];              // exp(s)
__device__ float4 g_ES2[ROWS];              // exp(0.2 s)
__device__ float4 g_ED [ROWS];              // exp(d)
__device__ float4 g_ED2[ROWS];              // exp(0.2 d)
__device__ int    g_cnt[Nn * Nn];           // edge multiplicity matrix

// ---------------------------------------------------------------------------
// Kernel A: fold weight matrices: M = [W_lin@a_src | W_lin@a_dst | W_edge@a_edge]
// ---------------------------------------------------------------------------
__global__ void compute_M_kernel(const float* __restrict__ W_lin,
                                 const float* __restrict__ a_src,
                                 const float* __restrict__ a_dst,
                                 const float* __restrict__ W_edge,
                                 const float* __restrict__ a_edge) {
    int f = threadIdx.x;   // 0..127
    float accS[4] = {0,0,0,0}, accD[4] = {0,0,0,0}, accE[4] = {0,0,0,0};
    for (int c = 0; c < Cc; c++) {
        float w = W_lin[f * Cc + c];
        #pragma unroll
        for (int h = 0; h < 4; h++) {
            accS[h] += w * a_src[c * Hh + h];
            accD[h] += w * a_dst[c * Hh + h];
        }
    }
    for (int d = 0; d < Ef; d++) {
        float w = W_edge[f * Ef + d];
        #pragma unroll
        for (int h = 0; h < 4; h++) accE[h] += w * a_edge[d * Hh + h];
    }
    #pragma unroll
    for (int h = 0; h < 4; h++) {
        g_M[f * 12 + h]     = accS[h];
        g_M[f * 12 + 4 + h] = accD[h];
        g_M[f * 12 + 8 + h] = accE[h];
    }
}

// ---------------------------------------------------------------------------
// Kernel B: per-row projections + exponentials. One warp per row.
// ---------------------------------------------------------------------------
__global__ void precompute_rows_kernel(const float* __restrict__ src) {
    __shared__ float sM[Fin * 12];
    for (int t = threadIdx.x; t < Fin * 12; t += blockDim.x) sM[t] = g_M[t];
    __syncthreads();

    int gwarp  = (blockIdx.x * blockDim.x + threadIdx.x) >> 5;
    int lane   = threadIdx.x & 31;
    int nwarps = (gridDim.x * blockDim.x) >> 5;

    for (int r = gwarp; r < ROWS; r += nwarps) {
        const float4 sv = reinterpret_cast<const float4*>(src + (size_t)r * Fin)[lane];
        float acc[12];
        #pragma unroll
        for (int h = 0; h < 12; h++) acc[h] = 0.0f;

        float vals[4] = {sv.x, sv.y, sv.z, sv.w};
        #pragma unroll
        for (int k = 0; k < 4; k++) {
            int f = lane * 4 + k;
            float x = vals[k];
            #pragma unroll
            for (int h = 0; h < 12; h++) acc[h] += x * sM[f * 12 + h];
        }
        #pragma unroll
        for (int o = 16; o > 0; o >>= 1) {
            #pragma unroll
            for (int h = 0; h < 12; h++)
                acc[h] += __shfl_xor_sync(0xffffffffu, acc[h], o);
        }
        if (lane == 0) {
            float4 s = make_float4(acc[0], acc[1], acc[2],  acc[3]);
            float4 d = make_float4(acc[4], acc[5], acc[6],  acc[7]);
            float4 p = make_float4(acc[8], acc[9], acc[10], acc[11]);
            g_S[r] = s;  g_D[r] = d;  g_P[r] = p;
            g_ES [r] = make_float4(__expf(s.x), __expf(s.y), __expf(s.z), __expf(s.w));
            g_ES2[r] = make_float4(__expf(NEG*s.x), __expf(NEG*s.y), __expf(NEG*s.z), __expf(NEG*s.w));
            g_ED [r] = make_float4(__expf(d.x), __expf(d.y), __expf(d.z), __expf(d.w));
            g_ED2[r] = make_float4(__expf(NEG*d.x), __expf(NEG*d.y), __expf(NEG*d.z), __expf(NEG*d.w));
        }
    }
}

// ---------------------------------------------------------------------------
// Kernel C: zero the edge-count matrix (int4 stores)
// ---------------------------------------------------------------------------
__global__ void zero_cnt_kernel() {
    int idx = blockIdx.x * blockDim.x + threadIdx.x;   // 262144 threads
    reinterpret_cast<int4*>(g_cnt)[idx] = make_int4(0, 0, 0, 0);
}

// ---------------------------------------------------------------------------
// Kernel D: scatter edge multiplicities
// ---------------------------------------------------------------------------
__global__ void scatter_kernel(const int* __restrict__ edge_index, int E) {
    int e = blockIdx.x * blockDim.x + threadIdx.x;
    if (e < E) {
        int i = edge_index[e];
        int j = edge_index[E + e];
        atomicAdd(&g_cnt[i * Nn + j], 1);
    }
}

// ---------------------------------------------------------------------------
// Kernel E: main output kernel.
// Block = (i, b); 256 threads x 4 j's each. 134 MB of streaming writes.
// Non-edge path: softmax from precomputed exp products (no MUFU.EX2).
// Edge path (~3% of pairs): direct __expf on the full value.
// ---------------------------------------------------------------------------
__global__ __launch_bounds__(256) void attn_kernel(float4* __restrict__ out) {
    const int i = blockIdx.x;
    const int b = blockIdx.y;
    const int ri = b * Nn + i;

    const float4 s4  = __ldg(&g_S[ri]);
    const float4 p4  = __ldg(&g_P[ri]);
    const float4 es  = __ldg(&g_ES[ri]);
    const float4 es2 = __ldg(&g_ES2[ri]);

    const int*    crow = g_cnt + i * Nn;
    float4* __restrict__ orow = out + ((size_t)(b * Nn + i)) * Nn;

    #pragma unroll
    for (int k = 0; k < 4; k++) {
        const int j  = threadIdx.x + k * 256;
        const int rj = b * Nn + j;
        const int c  = __ldg(crow + j);

        float4 e;
        if (c == 0) {
            const float4 ed  = __ldg(&g_ED[rj]);
            const float4 ed2 = __ldg(&g_ED2[rj]);
            // sign(s+d) <=> exp(s)exp(d) > 1
            float px = es.x * ed.x;  e.x = (px > 1.0f) ? px : es2.x * ed2.x;
            float py = es.y * ed.y;  e.y = (py > 1.0f) ? py : es2.y * ed2.y;
            float pz = es.z * ed.z;  e.z = (pz > 1.0f) ? pz : es2.z * ed2.z;
            float pw = es.w * ed.w;  e.w = (pw > 1.0f) ? pw : es2.w * ed2.w;
        } else {
            const float4 dv = __ldg(&g_D[rj]);
            const float4 pv = __ldg(&g_P[rj]);
            const float fc = (float)c;
            float vx = s4.x + dv.x + fc * (p4.x - pv.x);
            float vy = s4.y + dv.y + fc * (p4.y - pv.y);
            float vz = s4.z + dv.z + fc * (p4.z - pv.z);
            float vw = s4.w + dv.w + fc * (p4.w - pv.w);
            vx = (vx > 0.0f) ? vx : NEG * vx;
            vy = (vy > 0.0f) ? vy : NEG * vy;
            vz = (vz > 0.0f) ? vz : NEG * vz;
            vw = (vw > 0.0f) ? vw : NEG * vw;
            e.x = __expf(vx); e.y = __expf(vy); e.z = __expf(vz); e.w = __expf(vw);
        }

        const float sum = (e.x + e.y) + (e.z + e.w);
        const float inv = __fdividef(1.0f, sum);
        const float4 o  = make_float4(e.x * inv, e.y * inv, e.z * inv, e.w * inv);
        __stcs(orow + j, o);   // streaming store — output never re-read
    }
}

// ---------------------------------------------------------------------------
// Launch
// Inputs (metadata order): src, edge_index, W_lin, a_src, a_dst, W_edge, a_edge
// ---------------------------------------------------------------------------
extern "C" void kernel_launch(void* const* d_in, const int* in_sizes, int n_in,
                              void* d_out, int out_size) {
    const float* src        = (const float*)d_in[0];
    const int*   edge_index = (const int*)  d_in[1];
    const float* W_lin      = (const float*)d_in[2];
    const float* a_src      = (const float*)d_in[3];
    const float* a_dst      = (const float*)d_in[4];
    const float* W_edge     = (const float*)d_in[5];
    const float* a_edge     = (const float*)d_in[6];
    const int E = in_sizes[1] / 2;

    compute_M_kernel<<<1, 128>>>(W_lin, a_src, a_dst, W_edge, a_edge);
    precompute_rows_kernel<<<128, 256>>>(src);
    zero_cnt_kernel<<<(Nn * Nn / 4) / 256, 256>>>();
    scatter_kernel<<<(E + 255) / 256, 256>>>(edge_index, E);
    attn_kernel<<<dim3(Nn, Bn), 256>>>((float4*)d_out);
}

// round 5
// speedup vs baseline: 1.2742x; 1.2742x over previous
#include <cuda_runtime.h>
#include <cuda_bf16.h>
#include <cstdint>

// Problem constants (fixed shapes per reference)
#define Bn   8
#define Nn   1024
#define Fin  128
#define Cc   128
#define Ef   64
#define Hh   4
#define NEG  0.2f
#define ROWS (Bn * Nn)          // 8192
#define ICHUNK 16               // i-rows per block in main kernel

// Scratch (device globals — no allocation allowed)
__device__ float  g_M[Fin * 12];            // cols 0-3: As, 4-7: Ad, 8-11: Ae
__device__ float4 g_S [ROWS];               // s  = src @ As
__device__ float4 g_D [ROWS];               // d  = src @ Ad
__device__ float4 g_P [ROWS];               // p  = src @ Ae
__device__ float4 g_ES [ROWS];              // exp(s)
__device__ float4 g_ES2[ROWS];              // exp(0.2 s)
__device__ float4 g_ED [ROWS];              // exp(d)
__device__ float4 g_ED2[ROWS];              // exp(0.2 d)
__device__ int    g_cnt[Nn * Nn];           // edge multiplicity matrix

// ---------------------------------------------------------------------------
// Kernel A: fold weights. Block k (0..11) computes column k of
// M = [W_lin@a_src | W_lin@a_dst | W_edge@a_edge], thread f = row.
// ---------------------------------------------------------------------------
__global__ void compute_M_kernel(const float* __restrict__ W_lin,
                                 const float* __restrict__ a_src,
                                 const float* __restrict__ a_dst,
                                 const float* __restrict__ W_edge,
                                 const float* __restrict__ a_edge) {
    const int k = blockIdx.x;      // 0..11
    const int f = threadIdx.x;     // 0..127
    float acc = 0.0f;
    if (k < 4) {
        const int h = k;
        for (int c = 0; c < Cc; c++) acc += W_lin[f * Cc + c] * a_src[c * Hh + h];
    } else if (k < 8) {
        const int h = k - 4;
        for (int c = 0; c < Cc; c++) acc += W_lin[f * Cc + c] * a_dst[c * Hh + h];
    } else {
        const int h = k - 8;
        for (int d = 0; d < Ef; d++) acc += W_edge[f * Ef + d] * a_edge[d * Hh + h];
    }
    g_M[f * 12 + k] = acc;
}

// ---------------------------------------------------------------------------
// Kernel B: per-row projections + exponentials (warp per row).
// Also zeroes the edge-count matrix (grid-stride int4 stores).
// ---------------------------------------------------------------------------
__global__ void precompute_rows_kernel(const float* __restrict__ src) {
    // zero g_cnt: 262144 int4 over 32768 threads = 8 each
    {
        int t = blockIdx.x * blockDim.x + threadIdx.x;
        int nthreads = gridDim.x * blockDim.x;
        int4* c4 = reinterpret_cast<int4*>(g_cnt);
        for (int idx = t; idx < (Nn * Nn) / 4; idx += nthreads)
            c4[idx] = make_int4(0, 0, 0, 0);
    }

    __shared__ float sM[Fin * 12];
    for (int t = threadIdx.x; t < Fin * 12; t += blockDim.x) sM[t] = g_M[t];
    __syncthreads();

    int gwarp  = (blockIdx.x * blockDim.x + threadIdx.x) >> 5;
    int lane   = threadIdx.x & 31;
    int nwarps = (gridDim.x * blockDim.x) >> 5;

    for (int r = gwarp; r < ROWS; r += nwarps) {
        const float4 sv = reinterpret_cast<const float4*>(src + (size_t)r * Fin)[lane];
        float acc[12];
        #pragma unroll
        for (int h = 0; h < 12; h++) acc[h] = 0.0f;

        float vals[4] = {sv.x, sv.y, sv.z, sv.w};
        #pragma unroll
        for (int k = 0; k < 4; k++) {
            int f = lane * 4 + k;
            float x = vals[k];
            #pragma unroll
            for (int h = 0; h < 12; h++) acc[h] += x * sM[f * 12 + h];
        }
        #pragma unroll
        for (int o = 16; o > 0; o >>= 1) {
            #pragma unroll
            for (int h = 0; h < 12; h++)
                acc[h] += __shfl_xor_sync(0xffffffffu, acc[h], o);
        }
        if (lane == 0) {
            float4 s = make_float4(acc[0], acc[1], acc[2],  acc[3]);
            float4 d = make_float4(acc[4], acc[5], acc[6],  acc[7]);
            float4 p = make_float4(acc[8], acc[9], acc[10], acc[11]);
            g_S[r] = s;  g_D[r] = d;  g_P[r] = p;
            g_ES [r] = make_float4(__expf(s.x), __expf(s.y), __expf(s.z), __expf(s.w));
            g_ES2[r] = make_float4(__expf(NEG*s.x), __expf(NEG*s.y), __expf(NEG*s.z), __expf(NEG*s.w));
            g_ED [r] = make_float4(__expf(d.x), __expf(d.y), __expf(d.z), __expf(d.w));
            g_ED2[r] = make_float4(__expf(NEG*d.x), __expf(NEG*d.y), __expf(NEG*d.z), __expf(NEG*d.w));
        }
    }
}

// ---------------------------------------------------------------------------
// Kernel C: scatter edge multiplicities
// ---------------------------------------------------------------------------
__global__ void scatter_kernel(const int* __restrict__ edge_index, int E) {
    int e = blockIdx.x * blockDim.x + threadIdx.x;
    if (e < E) {
        int i = edge_index[e];
        int j = edge_index[E + e];
        atomicAdd(&g_cnt[i * Nn + j], 1);
    }
}

// ---------------------------------------------------------------------------
// Kernel D: main streaming kernel. Branch-free, edge-oblivious.
// Grid (j-tile=4, i-chunk=64, b=8). Thread owns one j: ed/ed2 live in
// registers; loop over ICHUNK i-values reading only a broadcast es/es2.
// exp(leaky(s+d)) = max(exp(s)exp(d), exp(.2s)exp(.2d))  [both >1 iff s+d>0]
// ---------------------------------------------------------------------------
__global__ __launch_bounds__(256) void attn_main_kernel(float4* __restrict__ out) {
    const int j  = blockIdx.x * 256 + threadIdx.x;
    const int i0 = blockIdx.y * ICHUNK;
    const int b  = blockIdx.z;
    const int rj = b * Nn + j;

    const float4 ed  = __ldg(&g_ED [rj]);
    const float4 ed2 = __ldg(&g_ED2[rj]);

    const float4* __restrict__ esrow  = g_ES  + b * Nn + i0;
    const float4* __restrict__ es2row = g_ES2 + b * Nn + i0;
    float4* __restrict__ optr = out + ((size_t)(b * Nn + i0)) * Nn + j;

    #pragma unroll
    for (int i = 0; i < ICHUNK; i++) {
        const float4 es  = __ldg(esrow  + i);   // broadcast across warp
        const float4 es2 = __ldg(es2row + i);

        float4 e;
        e.x = fmaxf(es.x * ed.x, es2.x * ed2.x);
        e.y = fmaxf(es.y * ed.y, es2.y * ed2.y);
        e.z = fmaxf(es.z * ed.z, es2.z * ed2.z);
        e.w = fmaxf(es.w * ed.w, es2.w * ed2.w);

        const float inv = __fdividef(1.0f, (e.x + e.y) + (e.z + e.w));
        __stcs(optr + (size_t)i * Nn,
               make_float4(e.x * inv, e.y * inv, e.z * inv, e.w * inv));
    }
}

// ---------------------------------------------------------------------------
// Kernel E: edge fixup. One thread per (edge, batch); overwrites the quad
// at (b,i,j) with the exact edge-aware value. Duplicate edges write
// identical values (multiplicity read from g_cnt), so races are benign.
// ---------------------------------------------------------------------------
__global__ void fixup_kernel(const int* __restrict__ edge_index, int E,
                             float4* __restrict__ out) {
    int t = blockIdx.x * blockDim.x + threadIdx.x;
    if (t >= E * Bn) return;
    const int e = t % E;
    const int b = t / E;
    const int i = edge_index[e];
    const int j = edge_index[E + e];
    const float c = (float)g_cnt[i * Nn + j];

    const int ri = b * Nn + i, rj = b * Nn + j;
    const float4 s  = __ldg(&g_S[ri]);
    const float4 pi = __ldg(&g_P[ri]);
    const float4 d  = __ldg(&g_D[rj]);
    const float4 pj = __ldg(&g_P[rj]);

    float vx = s.x + d.x + c * (pi.x - pj.x);
    float vy = s.y + d.y + c * (pi.y - pj.y);
    float vz = s.z + d.z + c * (pi.z - pj.z);
    float vw = s.w + d.w + c * (pi.w - pj.w);
    vx = (vx > 0.0f) ? vx : NEG * vx;
    vy = (vy > 0.0f) ? vy : NEG * vy;
    vz = (vz > 0.0f) ? vz : NEG * vz;
    vw = (vw > 0.0f) ? vw : NEG * vw;

    float4 ev = make_float4(__expf(vx), __expf(vy), __expf(vz), __expf(vw));
    const float inv = __fdividef(1.0f, (ev.x + ev.y) + (ev.z + ev.w));
    out[((size_t)(b * Nn + i)) * Nn + j] =
        make_float4(ev.x * inv, ev.y * inv, ev.z * inv, ev.w * inv);
}

// ---------------------------------------------------------------------------
// Launch
// Inputs (metadata order): src, edge_index, W_lin, a_src, a_dst, W_edge, a_edge
// ---------------------------------------------------------------------------
extern "C" void kernel_launch(void* const* d_in, const int* in_sizes, int n_in,
                              void* d_out, int out_size) {
    const float* src        = (const float*)d_in[0];
    const int*   edge_index = (const int*)  d_in[1];
    const float* W_lin      = (const float*)d_in[2];
    const float* a_src      = (const float*)d_in[3];
    const float* a_dst      = (const float*)d_in[4];
    const float* W_edge     = (const float*)d_in[5];
    const float* a_edge     = (const float*)d_in[6];
    const int E = in_sizes[1] / 2;

    compute_M_kernel<<<12, 128>>>(W_lin, a_src, a_dst, W_edge, a_edge);
    precompute_rows_kernel<<<128, 256>>>(src);   // also zeroes g_cnt
    scatter_kernel<<<(E + 255) / 256, 256>>>(edge_index, E);
    attn_main_kernel<<<dim3(Nn / 256, Nn / ICHUNK, Bn), 256>>>((float4*)d_out);
    fixup_kernel<<<(E * Bn + 255) / 256, 256>>>(edge_index, E, (float4*)d_out);
}